// round 17
// baseline (speedup 1.0000x reference)
#include <cuda_runtime.h>
#include <cuda_fp16.h>

// FastQuantumLLMOptimized: per-position cross-head attention, tensor-core path.
// x: [16384, 32, 128] f32, patterns: [32,128] f32.
//   xh = x_pos * patterns ; s = xh xh^T / sqrt(128); a = softmax(s); out = a xh
//
// TWO positions per CTA (2 warps), software-pipelined with cp.async:
//   cp.async pos0 -> convert -> [issue cp.async pos1] -> compute0
//   -> wait -> convert -> compute1
// The 16KB x-read of position 1 overlaps position 0's whole compute span,
// keeping DRAM busy (the 90.6us kernel idled DRAM during compute).
//
// GEMMs via mma.sync.m16n8k16 (HMMA), xh quantized to fp16 once:
//   GEMM1: scores = hi*hi^T ; GEMM2: out = attn_fp16 * hi
// Softmax on fp32 C-fragments; attn C-frags repack in-register to GEMM2
// A-frags. Warp w owns score/output rows 16w..16w+15.
//
// smem: raw x f32 (16KB, cp.async target) + xh fp16 (8KB, 256B rows,
// 16B-granule XOR swizzle g^(h&7) -> conflict-free ldmatrix).

#define NHEADS 32
#define HD 128
#define SCALE 0.08838834764831845f   // 1/sqrt(128)

__device__ __forceinline__ unsigned smem_u32(const void* p) {
    unsigned r;
    asm("{ .reg .u64 t; cvta.to.shared.u64 t, %1; cvt.u32.u64 %0, t; }"
        : "=r"(r) : "l"(p));
    return r;
}
__device__ __forceinline__ void cp_async16(unsigned s, const void* g) {
    asm volatile("cp.async.cg.shared.global [%0], [%1], 16;"
                 :: "r"(s), "l"(g));
}
__device__ __forceinline__ void cp_commit() {
    asm volatile("cp.async.commit_group;");
}
__device__ __forceinline__ void cp_wait0() {
    asm volatile("cp.async.wait_group 0;");
}
__device__ __forceinline__ void ldsm4(unsigned a, unsigned* r) {
    asm volatile("ldmatrix.sync.aligned.m8n8.x4.shared.b16 {%0,%1,%2,%3}, [%4];"
                 : "=r"(r[0]), "=r"(r[1]), "=r"(r[2]), "=r"(r[3]) : "r"(a));
}
__device__ __forceinline__ void ldsm4t(unsigned a, unsigned* r) {
    asm volatile("ldmatrix.sync.aligned.m8n8.x4.trans.shared.b16 {%0,%1,%2,%3}, [%4];"
                 : "=r"(r[0]), "=r"(r[1]), "=r"(r[2]), "=r"(r[3]) : "r"(a));
}
__device__ __forceinline__ void mma16816(float* c, const unsigned* a, const unsigned* b) {
    asm volatile("mma.sync.aligned.m16n8k16.row.col.f32.f16.f16.f32 "
                 "{%0,%1,%2,%3}, {%4,%5,%6,%7}, {%8,%9}, {%0,%1,%2,%3};"
                 : "+f"(c[0]), "+f"(c[1]), "+f"(c[2]), "+f"(c[3])
                 : "r"(a[0]), "r"(a[1]), "r"(a[2]), "r"(a[3]),
                   "r"(b[0]), "r"(b[1]));
}
// pack {lo, hi} fp32 -> f16x2 register (lo in lower half)
__device__ __forceinline__ unsigned pk_h2(float lo, float hi) {
    unsigned r;
    asm("cvt.rn.f16x2.f32 %0, %1, %2;" : "=r"(r) : "f"(hi), "f"(lo));
    return r;
}

__global__ __launch_bounds__(64, 9)
void fq_attn_kernel(const float* __restrict__ x,
                    const float* __restrict__ patterns,
                    float* __restrict__ out)
{
    __shared__ __align__(16) float  s_raw[NHEADS * HD];  // 16 KB (cp.async dst)
    __shared__ __align__(16) __half s_hf [NHEADS * HD];  //  8 KB

    const int tid  = threadIdx.x;
    const int lane = tid & 31;
    const int w    = tid >> 5;

    const unsigned rawu = smem_u32(s_raw);
    const unsigned hfu  = smem_u32(s_hf);
    const float4*  p4   = reinterpret_cast<const float4*>(patterns);
    const float4*  raw4 = reinterpret_cast<const float4*>(s_raw);

    // ---------------- prologue: cp.async load position 0 -------------------
    {
        const float4* src = reinterpret_cast<const float4*>(
            x + (2LL * blockIdx.x) * (NHEADS * HD));
        #pragma unroll
        for (int i = 0; i < 16; i++) {
            const int idx = tid + i * 64;
            cp_async16(rawu + idx * 16, src + idx);
        }
        cp_commit();
    }
    cp_wait0();
    __syncthreads();

    #pragma unroll 1
    for (int it = 0; it < 2; it++) {
        const long long pos = 2LL * blockIdx.x + it;

        // ------------- convert: raw f32 -> xh fp16 (swizzled) --------------
        // warp w handles rows 16w..16w+15; lane owns float4 column `lane`.
        {
            const int g   = lane >> 1;
            const int sub = (lane & 1) * 4;
            #pragma unroll 4
            for (int i = 0; i < 16; i++) {
                const int h = 16 * w + i;
                float4 xv = raw4[h * 32 + lane];
                float4 pv = __ldg(&p4[h * 32 + lane]);
                const int idx = h * 128 + ((g ^ (h & 7)) << 3) + sub;
                uint2 hv;
                hv.x = pk_h2(xv.x * pv.x, xv.y * pv.y);
                hv.y = pk_h2(xv.z * pv.z, xv.w * pv.w);
                *reinterpret_cast<uint2*>(&s_hf[idx]) = hv;
            }
        }
        __syncthreads();   // hf ready; raw free

        // ------------- issue next position's cp.async (overlaps compute) ---
        if (it == 0) {
            const float4* src = reinterpret_cast<const float4*>(
                x + (2LL * blockIdx.x + 1) * (NHEADS * HD));
            #pragma unroll
            for (int i = 0; i < 16; i++) {
                const int idx = tid + i * 64;
                cp_async16(rawu + idx * 16, src + idx);
            }
            cp_commit();
        }

        // ------------- GEMM1: S rows 16w.. = hi*hi^T -----------------------
        float c1[4][4];
        #pragma unroll
        for (int nt = 0; nt < 4; nt++)
            #pragma unroll
            for (int z = 0; z < 4; z++) c1[nt][z] = 0.0f;

        {
            const int rowA = 16 * w + (lane & 7) + ((lane >> 3) & 1) * 8;
            const int rowB = (lane & 7) + (lane >> 4) * 8;
            #pragma unroll 2
            for (int kt = 0; kt < 8; kt++) {
                const int granA = 2 * kt + (lane >> 4);
                const int granB = 2 * kt + ((lane >> 3) & 1);
                unsigned ah[4], bh[2][4];
                {
                    const unsigned off = rowA * 256 + ((granA ^ (rowA & 7)) << 4);
                    ldsm4(hfu + off, ah);
                }
                #pragma unroll
                for (int p = 0; p < 2; p++) {
                    const int row = 16 * p + rowB;
                    const unsigned off = row * 256 + ((granB ^ (row & 7)) << 4);
                    ldsm4(hfu + off, bh[p]);
                }
                #pragma unroll
                for (int nt = 0; nt < 4; nt++)
                    mma16816(c1[nt], ah, &bh[nt >> 1][(nt & 1) * 2]);
            }
        }

        // ------------- softmax on C fragments ------------------------------
        #pragma unroll
        for (int rh = 0; rh < 2; rh++) {
            float v[8];
            #pragma unroll
            for (int nt = 0; nt < 4; nt++) {
                v[2 * nt]     = c1[nt][2 * rh]     * SCALE;
                v[2 * nt + 1] = c1[nt][2 * rh + 1] * SCALE;
            }
            float m = v[0];
            #pragma unroll
            for (int j = 1; j < 8; j++) m = fmaxf(m, v[j]);
            m = fmaxf(m, __shfl_xor_sync(0xffffffffu, m, 1));
            m = fmaxf(m, __shfl_xor_sync(0xffffffffu, m, 2));
            float s = 0.0f;
            #pragma unroll
            for (int j = 0; j < 8; j++) { v[j] = __expf(v[j] - m); s += v[j]; }
            s += __shfl_xor_sync(0xffffffffu, s, 1);
            s += __shfl_xor_sync(0xffffffffu, s, 2);
            const float inv = 1.0f / s;
            #pragma unroll
            for (int nt = 0; nt < 4; nt++) {
                c1[nt][2 * rh]     = v[2 * nt]     * inv;
                c1[nt][2 * rh + 1] = v[2 * nt + 1] * inv;
            }
        }

        // ------------- repack attn C-frags -> GEMM2 A-frags ----------------
        unsigned a2[2][4];
        #pragma unroll
        for (int kt2 = 0; kt2 < 2; kt2++) {
            a2[kt2][0] = pk_h2(c1[2 * kt2][0],     c1[2 * kt2][1]);
            a2[kt2][1] = pk_h2(c1[2 * kt2][2],     c1[2 * kt2][3]);
            a2[kt2][2] = pk_h2(c1[2 * kt2 + 1][0], c1[2 * kt2 + 1][1]);
            a2[kt2][3] = pk_h2(c1[2 * kt2 + 1][2], c1[2 * kt2 + 1][3]);
        }

        // ------------- GEMM2: out rows 16w.. = attn * hi -------------------
        {
            float* outp = out + pos * (NHEADS * HD);
            const int q = lane & 3;
            const int r = lane >> 2;

            #pragma unroll
            for (int nc = 0; nc < 4; nc++) {
                float c2[4][4];
                #pragma unroll
                for (int dt = 0; dt < 4; dt++)
                    #pragma unroll
                    for (int z = 0; z < 4; z++) c2[dt][z] = 0.0f;

                #pragma unroll
                for (int kt2 = 0; kt2 < 2; kt2++) {
                    const int rowG = 16 * kt2 + (lane & 7) + ((lane >> 3) & 1) * 8;
                    unsigned b2h[2][4];
                    #pragma unroll
                    for (int p = 0; p < 2; p++) {
                        const int gran = 4 * nc + 2 * p + (lane >> 4);
                        const unsigned off = rowG * 256 + ((gran ^ (rowG & 7)) << 4);
                        ldsm4t(hfu + off, b2h[p]);
                    }
                    #pragma unroll
                    for (int dt = 0; dt < 4; dt++)
                        mma16816(c2[dt], a2[kt2], &b2h[dt >> 1][(dt & 1) * 2]);
                }

                #pragma unroll
                for (int dt = 0; dt < 4; dt++) {
                    const int col  = 32 * nc + 8 * dt + 2 * q;
                    const int row0 = 16 * w + r;
                    *reinterpret_cast<float2*>(&outp[row0 * HD + col])
                        = make_float2(c2[dt][0], c2[dt][1]);
                    *reinterpret_cast<float2*>(&outp[(row0 + 8) * HD + col])
                        = make_float2(c2[dt][2], c2[dt][3]);
                }
            }
        }

        // ------------- barrier into iteration 1 ----------------------------
        if (it == 0) {
            cp_wait0();        // raw(pos1) landed
            __syncthreads();   // all warps done reading hf(pos0)
        }
    }
}

extern "C" void kernel_launch(void* const* d_in, const int* in_sizes, int n_in,
                              void* d_out, int out_size) {
    const float* x        = (const float*)d_in[0];
    const float* patterns = (const float*)d_in[1];
    float* out            = (float*)d_out;
    const int positions   = in_sizes[0] / (NHEADS * HD);   // 16384 (even)
    fq_attn_kernel<<<positions / 2, 64>>>(x, patterns, out);
}